// round 5
// baseline (speedup 1.0000x reference)
#include <cuda_runtime.h>
#include <float.h>

// Problem constants (fixed by reference setup_inputs)
#define LN   1024      // sequence length L
#define DD   768       // hidden d
#define HH   12        // heads
#define EE   32        // entities
#define MM   4         // mentions
#define RR   256       // relations per doc
#define NMAX 4         // batch

// Scratch (device globals -- no allocation allowed)
__device__ float g_e_emb[NMAX * EE * DD];            // (n,E,d)
__device__ float g_e_att[NMAX * EE * HH * LN];       // (n,E,h,L)
__device__ float g_ht_att[NMAX * RR * LN];           // (n,R,L)

// ---------------------------------------------------------------------------
// f32x2 helpers
// ---------------------------------------------------------------------------
__device__ __forceinline__ void ffma2(unsigned long long& d,
                                      unsigned long long a,
                                      unsigned long long b)
{
    asm("fma.rn.f32x2 %0, %1, %2, %0;" : "+l"(d) : "l"(a), "l"(b));
}

// ---------------------------------------------------------------------------
// Kernel 1: e_emb[i,e,k] = logsumexp_m( mask>0 ? seq[i, pos+1, k] : -FLT_MAX )
// ---------------------------------------------------------------------------
__global__ void k_e_emb(const float* __restrict__ seq,
                        const int*   __restrict__ pos,
                        const float* __restrict__ mask,
                        int n)
{
    int idx = blockIdx.x * blockDim.x + threadIdx.x;
    int total = n * EE * DD;
    if (idx >= total) return;
    int k = idx % DD;
    int e = (idx / DD) % EE;
    int i = idx / (DD * EE);

    const int*   p  = pos  + (i * EE + e) * MM;
    const float* mk = mask + (i * EE + e) * MM;

    float v[MM];
    float mx = -FLT_MAX;
#pragma unroll
    for (int m = 0; m < MM; m++) {
        int pp = p[m] + 1;                       // OFFSET
        float x = seq[(i * LN + pp) * DD + k];
        if (mk[m] <= 0.0f) x = -FLT_MAX;
        v[m] = x;
        mx = fmaxf(mx, x);
    }
    float s = 0.0f;
#pragma unroll
    for (int m = 0; m < MM; m++) s += expf(v[m] - mx);
    g_e_emb[idx] = mx + logf(s);
}

// ---------------------------------------------------------------------------
// Kernel 2 (float4): e_att[i,e,hh,l] = sum_m mask*att[i,hh,pos+1,l] / cnt
// ---------------------------------------------------------------------------
__global__ void k_e_att(const float* __restrict__ att,
                        const int*   __restrict__ pos,
                        const float* __restrict__ mask,
                        int n)
{
    int idx = blockIdx.x * blockDim.x + threadIdx.x;     // over float4 elems
    int total = n * EE * HH * (LN / 4);
    if (idx >= total) return;
    int l4 = idx % (LN / 4);
    int hh = (idx / (LN / 4)) % HH;
    int e  = (idx / ((LN / 4) * HH)) % EE;
    int i  = idx / ((LN / 4) * HH * EE);

    const int*   p  = pos  + (i * EE + e) * MM;
    const float* mk = mask + (i * EE + e) * MM;
    const float4* att4 = (const float4*)att;

    float cnt = 0.0f;
    float4 s = make_float4(0.f, 0.f, 0.f, 0.f);
#pragma unroll
    for (int m = 0; m < MM; m++) {
        float mm = mk[m];
        cnt += mm;
        int pp = p[m] + 1;
        float4 a = att4[((size_t)(i * HH + hh) * LN + pp) * (LN / 4) + l4];
        s.x += mm * a.x; s.y += mm * a.y; s.z += mm * a.z; s.w += mm * a.w;
    }
    float inv = 1.0f / fmaxf(cnt, 1.0f);
    s.x *= inv; s.y *= inv; s.z *= inv; s.w *= inv;
    ((float4*)g_e_att)[idx] = s;
}

// ---------------------------------------------------------------------------
// Kernel 3 (float4): one block (256 thr) per (i,r).
// ht[l] = (1/H) sum_h eA[h,l]*eB[h,l];  ht /= (sum_l ht + 1e-5)
// ---------------------------------------------------------------------------
__global__ void k_ht_att(const int* __restrict__ hts, int n)
{
    int b = blockIdx.x;               // i*R + r
    int i = b / RR;
    int ha = hts[b * 2 + 0];
    int ta = hts[b * 2 + 1];

    const float4* A = (const float4*)(g_e_att + (size_t)(i * EE + ha) * HH * LN);
    const float4* B = (const float4*)(g_e_att + (size_t)(i * EE + ta) * HH * LN);
    int t = threadIdx.x;              // 256 threads, one float4 each

    float4 s = make_float4(0.f, 0.f, 0.f, 0.f);
#pragma unroll
    for (int hh = 0; hh < HH; hh++) {
        float4 a = A[hh * (LN / 4) + t];
        float4 c = B[hh * (LN / 4) + t];
        s.x += a.x * c.x; s.y += a.y * c.y; s.z += a.z * c.z; s.w += a.w * c.w;
    }
    const float invH = 1.0f / (float)HH;
    s.x *= invH; s.y *= invH; s.z *= invH; s.w *= invH;
    float local = s.x + s.y + s.z + s.w;

    __shared__ float red[8];
#pragma unroll
    for (int off = 16; off > 0; off >>= 1)
        local += __shfl_xor_sync(0xffffffffu, local, off);
    if ((t & 31) == 0) red[t >> 5] = local;
    __syncthreads();
    if (t < 32) {
        float x = (t < 8) ? red[t] : 0.0f;
#pragma unroll
        for (int off = 4; off > 0; off >>= 1)
            x += __shfl_xor_sync(0xffffffffu, x, off);
        if (t == 0) red[0] = x;
    }
    __syncthreads();
    float inv = 1.0f / (red[0] + 1e-5f);

    float4 o = make_float4(s.x * inv, s.y * inv, s.z * inv, s.w * inv);
    ((float4*)(g_ht_att + (size_t)b * LN))[t] = o;
}

// ---------------------------------------------------------------------------
// Kernel 4: rs plane SGEMM (f32x2) + fused hs/ts plane copy.
// C(i) [R x D] = ht_att(i) [R x L] * seq(i) [L x D]
// BM=64 BN=96 BK=32, 256 threads, thread tile 4 rows x 6 cols,
// COLUMN-packed f32x2 accumulators (pair = adjacent cols).
// A stored DUPLICATED in smem (As2[k][2m]=As2[k][2m+1]=A[m][k]); all smem
// reads are 8-byte LDS.64 (row strides 520B / 400B are 8B-aligned; the R4
// crash was a 16B ulonglong2 read against the 520B stride).
// Inner loop = 7 LDS.64 + 12 FFMA2, zero broadcast MOVs.
// grid = 8 x 4 x 4 = 128 blocks -> single wave on 148 SMs.
// ---------------------------------------------------------------------------
#define BMg 64
#define BNg 96
#define BKg 32
#define GT  256
#define APAD 2     // As2 row stride = 130 floats (spreads dup-store banks)
#define BPAD 4

__global__ __launch_bounds__(GT, 1) void k_gemm(const float* __restrict__ seq,
                                                const int*   __restrict__ hts,
                                                float* __restrict__ out, int n)
{
    __shared__ __align__(16) float As2[2][BKg][2 * BMg + APAD]; // duplicated A
    __shared__ __align__(16) float Bs[2][BKg][BNg + BPAD];

    int i = blockIdx.z;
    const float* Ad = g_ht_att + (size_t)i * RR * LN;   // R x L
    const float* Bd = seq      + (size_t)i * LN * DD;   // L x D
    size_t P = (size_t)n * RR * DD;
    float* Cd = out + 2 * P + (size_t)i * RR * DD;      // R x D

    int rowBase = blockIdx.y * BMg;
    int colBase = blockIdx.x * BNg;
    int tid = threadIdx.x;

    // ---- loader slots ----
    // A tile: 64 rows x 32 k = 512 float4; 2 per thread
    int aRow0 = tid >> 3,            aK0 = (tid & 7) * 4;
    int i1 = tid + GT; int aRow1 = i1 >> 3, aK1 = (i1 & 7) * 4;
    // B tile: 32 k x 96 cols = 768 float4; 3 per thread
    int bRow[3], bC[3];
#pragma unroll
    for (int s = 0; s < 3; s++) {
        int id = tid + s * GT;
        bRow[s] = id / 24;
        bC[s]   = (id % 24) * 4;
    }

    // ---- compute mapping: 4 rows (ty) x 6 cols (tx) per thread ----
    int ty = tid >> 4;     // 0..15 -> rows ty*4 .. ty*4+3
    int tx = tid & 15;     // 0..15 -> cols tx*6 .. tx*6+5

    unsigned long long acc[4][3];   // [row][col-pair]
#pragma unroll
    for (int r = 0; r < 4; r++)
#pragma unroll
        for (int p = 0; p < 3; p++) acc[r][p] = 0ull;

    // ---- initial global loads (k0 = 0) ----
    float4 ra0, ra1, rb[3];
    ra0 = *(const float4*)&Ad[(size_t)(rowBase + aRow0) * LN + aK0];
    ra1 = *(const float4*)&Ad[(size_t)(rowBase + aRow1) * LN + aK1];
#pragma unroll
    for (int s = 0; s < 3; s++)
        rb[s] = *(const float4*)&Bd[(size_t)bRow[s] * DD + colBase + bC[s]];

    int buf = 0;
    for (int k0 = 0; k0 < LN; k0 += BKg) {
        // store prefetched regs into smem buffer `buf` (A duplicated)
        {
            float2 d;
            d.x = d.y = ra0.x; *(float2*)&As2[buf][aK0 + 0][2 * aRow0] = d;
            d.x = d.y = ra0.y; *(float2*)&As2[buf][aK0 + 1][2 * aRow0] = d;
            d.x = d.y = ra0.z; *(float2*)&As2[buf][aK0 + 2][2 * aRow0] = d;
            d.x = d.y = ra0.w; *(float2*)&As2[buf][aK0 + 3][2 * aRow0] = d;
            d.x = d.y = ra1.x; *(float2*)&As2[buf][aK1 + 0][2 * aRow1] = d;
            d.x = d.y = ra1.y; *(float2*)&As2[buf][aK1 + 1][2 * aRow1] = d;
            d.x = d.y = ra1.z; *(float2*)&As2[buf][aK1 + 2][2 * aRow1] = d;
            d.x = d.y = ra1.w; *(float2*)&As2[buf][aK1 + 3][2 * aRow1] = d;
        }
#pragma unroll
        for (int s = 0; s < 3; s++)
            *(float4*)&Bs[buf][bRow[s]][bC[s]] = rb[s];
        __syncthreads();

        // prefetch next K-slab into registers (hidden under compute)
        int kn = k0 + BKg;
        if (kn < LN) {
            ra0 = *(const float4*)&Ad[(size_t)(rowBase + aRow0) * LN + kn + aK0];
            ra1 = *(const float4*)&Ad[(size_t)(rowBase + aRow1) * LN + kn + aK1];
#pragma unroll
            for (int s = 0; s < 3; s++)
                rb[s] = *(const float4*)&Bd[(size_t)(kn + bRow[s]) * DD + colBase + bC[s]];
        }

        // compute on buffer `buf`: 7 LDS.64 + 12 FFMA2 per kk (no broadcasts)
#pragma unroll
        for (int kk = 0; kk < BKg; kk++) {
            const float* ap = &As2[buf][kk][ty * 8];
            unsigned long long a0 = *(const unsigned long long*)(ap + 0);
            unsigned long long a1 = *(const unsigned long long*)(ap + 2);
            unsigned long long a2 = *(const unsigned long long*)(ap + 4);
            unsigned long long a3 = *(const unsigned long long*)(ap + 6);
            const float* bp = &Bs[buf][kk][tx * 6];
            unsigned long long b01 = *(const unsigned long long*)(bp + 0);
            unsigned long long b23 = *(const unsigned long long*)(bp + 2);
            unsigned long long b45 = *(const unsigned long long*)(bp + 4);
            ffma2(acc[0][0], a0, b01);
            ffma2(acc[0][1], a0, b23);
            ffma2(acc[0][2], a0, b45);
            ffma2(acc[1][0], a1, b01);
            ffma2(acc[1][1], a1, b23);
            ffma2(acc[1][2], a1, b45);
            ffma2(acc[2][0], a2, b01);
            ffma2(acc[2][1], a2, b23);
            ffma2(acc[2][2], a2, b45);
            ffma2(acc[3][0], a3, b01);
            ffma2(acc[3][1], a3, b23);
            ffma2(acc[3][2], a3, b45);
        }
        buf ^= 1;
        __syncthreads();
    }

    // ---- epilogue: acc[r][p] -> row rowBase+ty*4+r, cols colBase+tx*6+2p..+1
#pragma unroll
    for (int r = 0; r < 4; r++) {
        float* c = &Cd[(size_t)(rowBase + ty * 4 + r) * DD + colBase + tx * 6];
        *(unsigned long long*)(c + 0) = acc[r][0];
        *(unsigned long long*)(c + 2) = acc[r][1];
        *(unsigned long long*)(c + 4) = acc[r][2];
    }

    // ---- fused hs/ts plane copy for this block's (row, col) tile ----
    {
        const float4* emb4 = (const float4*)g_e_emb;
        float4* out4 = (float4*)out;
        size_t P4 = (size_t)n * RR * (DD / 4);
        // tile = 64 rows x 24 float4 cols = 1536 float4 per plane; 6 per thread
#pragma unroll
        for (int s = 0; s < 6; s++) {
            int idx = tid + s * GT;        // 0..1535
            int row = idx / 24;            // 0..63
            int c4  = idx % 24;
            int b = i * RR + rowBase + row;
            int ha = hts[b * 2 + 0];
            int ta = hts[b * 2 + 1];
            int col4 = colBase / 4 + c4;
            float4 vh = emb4[(size_t)(i * EE + ha) * (DD / 4) + col4];
            float4 vt = emb4[(size_t)(i * EE + ta) * (DD / 4) + col4];
            out4[(size_t)b * (DD / 4) + col4]      = vh;
            out4[P4 + (size_t)b * (DD / 4) + col4] = vt;
        }
    }
}

// ---------------------------------------------------------------------------
extern "C" void kernel_launch(void* const* d_in, const int* in_sizes, int n_in,
                              void* d_out, int out_size)
{
    const float* seq  = (const float*)d_in[0];   // (n, L, d)
    const float* att  = (const float*)d_in[1];   // (n, h, L, L)
    const int*   pos  = (const int*)  d_in[2];   // (n, E, M)
    const float* mask = (const float*)d_in[3];   // (n, E, M)
    const int*   hts  = (const int*)  d_in[4];   // (n, R, 2)
    float* out = (float*)d_out;

    int n = in_sizes[0] / (LN * DD);
    if (n > NMAX) n = NMAX;

    {   // e_emb
        int total = n * EE * DD;
        k_e_emb<<<(total + 255) / 256, 256>>>(seq, pos, mask, n);
    }
    {   // e_att (float4)
        int total = n * EE * HH * (LN / 4);
        k_e_att<<<(total + 255) / 256, 256>>>(att, pos, mask, n);
    }
    {   // ht_att
        k_ht_att<<<n * RR, 256>>>(hts, n);
    }
    {   // rs plane GEMM (f32x2, no-broadcast inner loop) + fused hs/ts copy
        dim3 grid(DD / BNg, RR / BMg, n);
        k_gemm<<<grid, GT>>>(seq, hts, out, n);
    }
}

// round 6
// speedup vs baseline: 1.3072x; 1.3072x over previous
#include <cuda_runtime.h>
#include <cuda_bf16.h>
#include <mma.h>
#include <float.h>

using namespace nvcuda;

// Problem constants (fixed by reference setup_inputs)
#define LN   1024      // sequence length L
#define DD   768       // hidden d
#define HH   12        // heads
#define EE   32        // entities
#define MM   4         // mentions
#define RR   256       // relations per doc
#define NMAX 4         // batch

// Scratch (device globals -- no allocation allowed)
__device__ float g_e_emb[NMAX * EE * DD];            // (n,E,d)
__device__ float g_e_att[NMAX * EE * HH * LN];       // (n,E,h,L)

// split-bf16 operands for the rs GEMM
__device__ __align__(16) __nv_bfloat16 g_A_hi[NMAX * RR * LN];   // ht_att hi
__device__ __align__(16) __nv_bfloat16 g_A_lo[NMAX * RR * LN];   // ht_att lo
__device__ __align__(16) __nv_bfloat16 g_B_hi[NMAX * LN * DD];   // seq hi
__device__ __align__(16) __nv_bfloat16 g_B_lo[NMAX * LN * DD];   // seq lo

// ---------------------------------------------------------------------------
// split helper: float4 -> 4 hi bf16 (uint2) + 4 lo bf16 (uint2)
// ---------------------------------------------------------------------------
__device__ __forceinline__ void split4(float4 v, uint2& uh, uint2& ul)
{
    __nv_bfloat162 h01 = __float22bfloat162_rn(make_float2(v.x, v.y));
    __nv_bfloat162 h23 = __float22bfloat162_rn(make_float2(v.z, v.w));
    float2 f01 = __bfloat1622float2(h01);
    float2 f23 = __bfloat1622float2(h23);
    __nv_bfloat162 l01 = __float22bfloat162_rn(make_float2(v.x - f01.x, v.y - f01.y));
    __nv_bfloat162 l23 = __float22bfloat162_rn(make_float2(v.z - f23.x, v.w - f23.y));
    uh.x = *(unsigned*)&h01; uh.y = *(unsigned*)&h23;
    ul.x = *(unsigned*)&l01; ul.y = *(unsigned*)&l23;
}

// ---------------------------------------------------------------------------
// Kernel 1: e_emb[i,e,k] = logsumexp_m( mask>0 ? seq[i, pos+1, k] : -FLT_MAX )
// ---------------------------------------------------------------------------
__global__ void k_e_emb(const float* __restrict__ seq,
                        const int*   __restrict__ pos,
                        const float* __restrict__ mask,
                        int n)
{
    int idx = blockIdx.x * blockDim.x + threadIdx.x;
    int total = n * EE * DD;
    if (idx >= total) return;
    int k = idx % DD;
    int e = (idx / DD) % EE;
    int i = idx / (DD * EE);

    const int*   p  = pos  + (i * EE + e) * MM;
    const float* mk = mask + (i * EE + e) * MM;

    float v[MM];
    float mx = -FLT_MAX;
#pragma unroll
    for (int m = 0; m < MM; m++) {
        int pp = p[m] + 1;                       // OFFSET
        float x = seq[(i * LN + pp) * DD + k];
        if (mk[m] <= 0.0f) x = -FLT_MAX;
        v[m] = x;
        mx = fmaxf(mx, x);
    }
    float s = 0.0f;
#pragma unroll
    for (int m = 0; m < MM; m++) s += expf(v[m] - mx);
    g_e_emb[idx] = mx + logf(s);
}

// ---------------------------------------------------------------------------
// Kernel 1b: split seq (fp32) into hi/lo bf16 planes for the GEMM B operand
// ---------------------------------------------------------------------------
__global__ void k_split_seq(const float4* __restrict__ seq4, int total4)
{
    int idx = blockIdx.x * blockDim.x + threadIdx.x;
    if (idx >= total4) return;
    uint2 uh, ul;
    split4(seq4[idx], uh, ul);
    ((uint2*)g_B_hi)[idx] = uh;
    ((uint2*)g_B_lo)[idx] = ul;
}

// ---------------------------------------------------------------------------
// Kernel 2 (float4): e_att[i,e,hh,l] = sum_m mask*att[i,hh,pos+1,l] / cnt
// ---------------------------------------------------------------------------
__global__ void k_e_att(const float* __restrict__ att,
                        const int*   __restrict__ pos,
                        const float* __restrict__ mask,
                        int n)
{
    int idx = blockIdx.x * blockDim.x + threadIdx.x;     // over float4 elems
    int total = n * EE * HH * (LN / 4);
    if (idx >= total) return;
    int l4 = idx % (LN / 4);
    int hh = (idx / (LN / 4)) % HH;
    int e  = (idx / ((LN / 4) * HH)) % EE;
    int i  = idx / ((LN / 4) * HH * EE);

    const int*   p  = pos  + (i * EE + e) * MM;
    const float* mk = mask + (i * EE + e) * MM;
    const float4* att4 = (const float4*)att;

    float cnt = 0.0f;
    float4 s = make_float4(0.f, 0.f, 0.f, 0.f);
#pragma unroll
    for (int m = 0; m < MM; m++) {
        float mm = mk[m];
        cnt += mm;
        int pp = p[m] + 1;
        float4 a = att4[((size_t)(i * HH + hh) * LN + pp) * (LN / 4) + l4];
        s.x += mm * a.x; s.y += mm * a.y; s.z += mm * a.z; s.w += mm * a.w;
    }
    float inv = 1.0f / fmaxf(cnt, 1.0f);
    s.x *= inv; s.y *= inv; s.z *= inv; s.w *= inv;
    ((float4*)g_e_att)[idx] = s;
}

// ---------------------------------------------------------------------------
// Kernel 3 (float4): one block (256 thr) per (i,r).
// ht[l] = (1/H) sum_h eA[h,l]*eB[h,l];  ht /= (sum_l ht + 1e-5)
// Writes the SPLIT bf16 hi/lo A operand for the GEMM.
// ---------------------------------------------------------------------------
__global__ void k_ht_att(const int* __restrict__ hts, int n)
{
    int b = blockIdx.x;               // i*R + r
    int i = b / RR;
    int ha = hts[b * 2 + 0];
    int ta = hts[b * 2 + 1];

    const float4* A = (const float4*)(g_e_att + (size_t)(i * EE + ha) * HH * LN);
    const float4* B = (const float4*)(g_e_att + (size_t)(i * EE + ta) * HH * LN);
    int t = threadIdx.x;              // 256 threads, one float4 each

    float4 s = make_float4(0.f, 0.f, 0.f, 0.f);
#pragma unroll
    for (int hh = 0; hh < HH; hh++) {
        float4 a = A[hh * (LN / 4) + t];
        float4 c = B[hh * (LN / 4) + t];
        s.x += a.x * c.x; s.y += a.y * c.y; s.z += a.z * c.z; s.w += a.w * c.w;
    }
    const float invH = 1.0f / (float)HH;
    s.x *= invH; s.y *= invH; s.z *= invH; s.w *= invH;
    float local = s.x + s.y + s.z + s.w;

    __shared__ float red[8];
#pragma unroll
    for (int off = 16; off > 0; off >>= 1)
        local += __shfl_xor_sync(0xffffffffu, local, off);
    if ((t & 31) == 0) red[t >> 5] = local;
    __syncthreads();
    if (t < 32) {
        float x = (t < 8) ? red[t] : 0.0f;
#pragma unroll
        for (int off = 4; off > 0; off >>= 1)
            x += __shfl_xor_sync(0xffffffffu, x, off);
        if (t == 0) red[0] = x;
    }
    __syncthreads();
    float inv = 1.0f / (red[0] + 1e-5f);

    float4 o = make_float4(s.x * inv, s.y * inv, s.z * inv, s.w * inv);
    uint2 uh, ul;
    split4(o, uh, ul);
    ((uint2*)(g_A_hi + (size_t)b * LN))[t] = uh;
    ((uint2*)(g_A_lo + (size_t)b * LN))[t] = ul;
}

// ---------------------------------------------------------------------------
// Kernel 4: rs plane GEMM on TENSOR CORES, split-bf16 3-term compensation:
//   C = Ahi*Bhi + Ahi*Blo + Alo*Bhi   (fp32 accum; ~1e-5 rel err)
// Block tile 64(M) x 96(N), BK=32, 8 warps as 4(M) x 2(N) -> warp tile 16x48
// (3 wmma 16x16 frags / warp). Double-buffered smem, register prefetch.
// grid = 8 x 4 x 4 = 128 blocks -> single wave. Fused hs/ts plane copy.
// ---------------------------------------------------------------------------
#define GBM 64
#define GBN 96
#define GBK 32
#define GT  256
#define LDA (GBK + 8)    // 40 bf16 = 80B row stride
#define LDB (GBN + 8)    // 104 bf16 = 208B row stride

__global__ __launch_bounds__(GT, 1) void k_gemm(const int* __restrict__ hts,
                                                float* __restrict__ out, int n)
{
    __shared__ __align__(16) __nv_bfloat16 Ah[2][GBM][LDA];
    __shared__ __align__(16) __nv_bfloat16 Al[2][GBM][LDA];
    __shared__ __align__(16) __nv_bfloat16 Bh[2][GBK][LDB];
    __shared__ __align__(16) __nv_bfloat16 Bl[2][GBK][LDB];

    int i = blockIdx.z;
    const __nv_bfloat16* Adh = g_A_hi + (size_t)i * RR * LN;
    const __nv_bfloat16* Adl = g_A_lo + (size_t)i * RR * LN;
    const __nv_bfloat16* Bdh = g_B_hi + (size_t)i * LN * DD;
    const __nv_bfloat16* Bdl = g_B_lo + (size_t)i * LN * DD;
    size_t P = (size_t)n * RR * DD;
    float* Cd = out + 2 * P + (size_t)i * RR * DD;      // R x D

    int rowBase = blockIdx.y * GBM;
    int colBase = blockIdx.x * GBN;
    int tid = threadIdx.x;
    int w   = tid >> 5;
    int wm  = w & 3;          // 0..3 : M slice (16 rows)
    int wn  = w >> 2;         // 0..1 : N slice (48 cols)

    // ---- loader slots (uint4 = 8 bf16) ----
    // A tile: 64 rows x 32 k = 256 slots, 1 per thread
    int aRow = tid >> 2, aK8 = (tid & 3) * 8;
    // B tile: 32 k x 96 n = 384 slots: slot tid, plus slot tid+256 for tid<128
    int b0Row = tid / 12,         b0N = (tid % 12) * 8;
    int b1Row = (tid + 256) / 12, b1N = ((tid + 256) % 12) * 8;
    bool hasB1 = tid < 128;

    wmma::fragment<wmma::accumulator, 16, 16, 16, float> acc[3];
#pragma unroll
    for (int j = 0; j < 3; j++) wmma::fill_fragment(acc[j], 0.0f);

    // ---- initial global loads (k0 = 0) ----
    uint4 rah, ral, rbh0, rbl0, rbh1, rbl1;
    rah = *(const uint4*)&Adh[(size_t)(rowBase + aRow) * LN + aK8];
    ral = *(const uint4*)&Adl[(size_t)(rowBase + aRow) * LN + aK8];
    rbh0 = *(const uint4*)&Bdh[(size_t)b0Row * DD + colBase + b0N];
    rbl0 = *(const uint4*)&Bdl[(size_t)b0Row * DD + colBase + b0N];
    if (hasB1) {
        rbh1 = *(const uint4*)&Bdh[(size_t)b1Row * DD + colBase + b1N];
        rbl1 = *(const uint4*)&Bdl[(size_t)b1Row * DD + colBase + b1N];
    }

    int buf = 0;
    for (int k0 = 0; k0 < LN; k0 += GBK) {
        // store prefetched regs into smem buffer `buf`
        *(uint4*)&Ah[buf][aRow][aK8] = rah;
        *(uint4*)&Al[buf][aRow][aK8] = ral;
        *(uint4*)&Bh[buf][b0Row][b0N] = rbh0;
        *(uint4*)&Bl[buf][b0Row][b0N] = rbl0;
        if (hasB1) {
            *(uint4*)&Bh[buf][b1Row][b1N] = rbh1;
            *(uint4*)&Bl[buf][b1Row][b1N] = rbl1;
        }
        __syncthreads();

        // prefetch next K-slab
        int kn = k0 + GBK;
        if (kn < LN) {
            rah = *(const uint4*)&Adh[(size_t)(rowBase + aRow) * LN + kn + aK8];
            ral = *(const uint4*)&Adl[(size_t)(rowBase + aRow) * LN + kn + aK8];
            rbh0 = *(const uint4*)&Bdh[(size_t)(kn + b0Row) * DD + colBase + b0N];
            rbl0 = *(const uint4*)&Bdl[(size_t)(kn + b0Row) * DD + colBase + b0N];
            if (hasB1) {
                rbh1 = *(const uint4*)&Bdh[(size_t)(kn + b1Row) * DD + colBase + b1N];
                rbl1 = *(const uint4*)&Bdl[(size_t)(kn + b1Row) * DD + colBase + b1N];
            }
        }

        // compute: 2 k-steps of 16
#pragma unroll
        for (int kk = 0; kk < GBK / 16; kk++) {
            wmma::fragment<wmma::matrix_a, 16, 16, 16, __nv_bfloat16, wmma::row_major> fa_h, fa_l;
            wmma::load_matrix_sync(fa_h, &Ah[buf][wm * 16][kk * 16], LDA);
            wmma::load_matrix_sync(fa_l, &Al[buf][wm * 16][kk * 16], LDA);
#pragma unroll
            for (int j = 0; j < 3; j++) {
                wmma::fragment<wmma::matrix_b, 16, 16, 16, __nv_bfloat16, wmma::row_major> fb_h, fb_l;
                const __nv_bfloat16* pbh = &Bh[buf][kk * 16][wn * 48 + j * 16];
                const __nv_bfloat16* pbl = &Bl[buf][kk * 16][wn * 48 + j * 16];
                wmma::load_matrix_sync(fb_h, pbh, LDB);
                wmma::load_matrix_sync(fb_l, pbl, LDB);
                wmma::mma_sync(acc[j], fa_h, fb_h, acc[j]);
                wmma::mma_sync(acc[j], fa_h, fb_l, acc[j]);
                wmma::mma_sync(acc[j], fa_l, fb_h, acc[j]);
            }
        }
        buf ^= 1;
        __syncthreads();
    }

    // ---- epilogue: store accumulators ----
#pragma unroll
    for (int j = 0; j < 3; j++) {
        float* c = &Cd[(size_t)(rowBase + wm * 16) * DD + colBase + wn * 48 + j * 16];
        wmma::store_matrix_sync(c, acc[j], DD, wmma::mem_row_major);
    }

    // ---- fused hs/ts plane copy for this block's (row, col) tile ----
    {
        const float4* emb4 = (const float4*)g_e_emb;
        float4* out4 = (float4*)out;
        size_t P4 = (size_t)n * RR * (DD / 4);
        // tile = 64 rows x 24 float4 cols = 1536 float4 per plane; 6 per thread
#pragma unroll
        for (int s = 0; s < 6; s++) {
            int idx = tid + s * GT;        // 0..1535
            int row = idx / 24;            // 0..63
            int c4  = idx % 24;
            int b = i * RR + rowBase + row;
            int ha = hts[b * 2 + 0];
            int ta = hts[b * 2 + 1];
            int col4 = colBase / 4 + c4;
            float4 vh = emb4[(size_t)(i * EE + ha) * (DD / 4) + col4];
            float4 vt = emb4[(size_t)(i * EE + ta) * (DD / 4) + col4];
            out4[(size_t)b * (DD / 4) + col4]      = vh;
            out4[P4 + (size_t)b * (DD / 4) + col4] = vt;
        }
    }
}

// ---------------------------------------------------------------------------
extern "C" void kernel_launch(void* const* d_in, const int* in_sizes, int n_in,
                              void* d_out, int out_size)
{
    const float* seq  = (const float*)d_in[0];   // (n, L, d)
    const float* att  = (const float*)d_in[1];   // (n, h, L, L)
    const int*   pos  = (const int*)  d_in[2];   // (n, E, M)
    const float* mask = (const float*)d_in[3];   // (n, E, M)
    const int*   hts  = (const int*)  d_in[4];   // (n, R, 2)
    float* out = (float*)d_out;

    int n = in_sizes[0] / (LN * DD);
    if (n > NMAX) n = NMAX;

    {   // e_emb
        int total = n * EE * DD;
        k_e_emb<<<(total + 255) / 256, 256>>>(seq, pos, mask, n);
    }
    {   // split seq into bf16 hi/lo
        int total4 = n * LN * DD / 4;
        k_split_seq<<<(total4 + 255) / 256, 256>>>((const float4*)seq, total4);
    }
    {   // e_att (float4)
        int total = n * EE * HH * (LN / 4);
        k_e_att<<<(total + 255) / 256, 256>>>(att, pos, mask, n);
    }
    {   // ht_att (writes split bf16 A)
        k_ht_att<<<n * RR, 256>>>(hts, n);
    }
    {   // rs plane GEMM (tensor cores, split-bf16) + fused hs/ts copy
        dim3 grid(DD / GBN, RR / GBM, n);
        k_gemm<<<grid, GT>>>(hts, out, n);
    }
}

// round 7
// speedup vs baseline: 1.4077x; 1.0768x over previous
#include <cuda_runtime.h>
#include <cuda_bf16.h>
#include <mma.h>
#include <float.h>

using namespace nvcuda;

// Problem constants (fixed by reference setup_inputs)
#define LN   1024      // sequence length L
#define DD   768       // hidden d
#define HH   12        // heads
#define EE   32        // entities
#define MM   4         // mentions
#define RR   256       // relations per doc
#define NMAX 4         // batch

// Scratch (device globals -- no allocation allowed)
__device__ float g_e_emb[NMAX * EE * DD];            // (n,E,d)
__device__ float g_e_att[NMAX * EE * HH * LN];       // (n,E,h,L)

// split-bf16 operands for the rs GEMM
__device__ __align__(16) __nv_bfloat16 g_A_hi[NMAX * RR * LN];   // ht_att hi
__device__ __align__(16) __nv_bfloat16 g_A_lo[NMAX * RR * LN];   // ht_att lo
__device__ __align__(16) __nv_bfloat16 g_B_hi[NMAX * LN * DD];   // seq hi
__device__ __align__(16) __nv_bfloat16 g_B_lo[NMAX * LN * DD];   // seq lo

// ---------------------------------------------------------------------------
// split helper: float4 -> 4 hi bf16 (uint2) + 4 lo bf16 (uint2)
// ---------------------------------------------------------------------------
__device__ __forceinline__ void split4(float4 v, uint2& uh, uint2& ul)
{
    __nv_bfloat162 h01 = __float22bfloat162_rn(make_float2(v.x, v.y));
    __nv_bfloat162 h23 = __float22bfloat162_rn(make_float2(v.z, v.w));
    float2 f01 = __bfloat1622float2(h01);
    float2 f23 = __bfloat1622float2(h23);
    __nv_bfloat162 l01 = __float22bfloat162_rn(make_float2(v.x - f01.x, v.y - f01.y));
    __nv_bfloat162 l23 = __float22bfloat162_rn(make_float2(v.z - f23.x, v.w - f23.y));
    uh.x = *(unsigned*)&h01; uh.y = *(unsigned*)&h23;
    ul.x = *(unsigned*)&l01; ul.y = *(unsigned*)&l23;
}

// ---------------------------------------------------------------------------
// Fused pre-kernel: e_emb | split_seq | e_att, dispatched by blockIdx range.
//   e_emb   : n*EE*DD        elems  ->  384 blocks (n=4)
//   split   : n*LN*DD/4      float4 -> 3072 blocks
//   e_att   : n*EE*HH*LN/4   float4 -> 1536 blocks
// ---------------------------------------------------------------------------
#define NB_EMB   ((NMAX * EE * DD) / 256)
#define NB_SPL   ((NMAX * LN * DD / 4) / 256)
#define NB_EATT  ((NMAX * EE * HH * (LN / 4)) / 256)

__global__ void k_pre(const float* __restrict__ seq,
                      const float* __restrict__ att,
                      const int*   __restrict__ pos,
                      const float* __restrict__ mask,
                      int n)
{
    int blk = blockIdx.x;
    if (blk < NB_EMB) {
        // ---- e_emb ----
        int idx = blk * 256 + threadIdx.x;
        int total = n * EE * DD;
        if (idx >= total) return;
        int k = idx % DD;
        int e = (idx / DD) % EE;
        int i = idx / (DD * EE);
        const int*   p  = pos  + (i * EE + e) * MM;
        const float* mk = mask + (i * EE + e) * MM;
        float v[MM];
        float mx = -FLT_MAX;
#pragma unroll
        for (int m = 0; m < MM; m++) {
            int pp = p[m] + 1;                       // OFFSET
            float x = seq[(i * LN + pp) * DD + k];
            if (mk[m] <= 0.0f) x = -FLT_MAX;
            v[m] = x;
            mx = fmaxf(mx, x);
        }
        float s = 0.0f;
#pragma unroll
        for (int m = 0; m < MM; m++) s += expf(v[m] - mx);
        g_e_emb[idx] = mx + logf(s);
    } else if (blk < NB_EMB + NB_SPL) {
        // ---- split seq into bf16 hi/lo ----
        int idx = (blk - NB_EMB) * 256 + threadIdx.x;
        int total4 = n * LN * DD / 4;
        if (idx >= total4) return;
        uint2 uh, ul;
        split4(((const float4*)seq)[idx], uh, ul);
        ((uint2*)g_B_hi)[idx] = uh;
        ((uint2*)g_B_lo)[idx] = ul;
    } else {
        // ---- e_att ----
        int idx = (blk - NB_EMB - NB_SPL) * 256 + threadIdx.x;
        int total = n * EE * HH * (LN / 4);
        if (idx >= total) return;
        int l4 = idx % (LN / 4);
        int hh = (idx / (LN / 4)) % HH;
        int e  = (idx / ((LN / 4) * HH)) % EE;
        int i  = idx / ((LN / 4) * HH * EE);
        const int*   p  = pos  + (i * EE + e) * MM;
        const float* mk = mask + (i * EE + e) * MM;
        const float4* att4 = (const float4*)att;
        float cnt = 0.0f;
        float4 s = make_float4(0.f, 0.f, 0.f, 0.f);
#pragma unroll
        for (int m = 0; m < MM; m++) {
            float mm = mk[m];
            cnt += mm;
            int pp = p[m] + 1;
            float4 a = att4[((size_t)(i * HH + hh) * LN + pp) * (LN / 4) + l4];
            s.x += mm * a.x; s.y += mm * a.y; s.z += mm * a.z; s.w += mm * a.w;
        }
        float inv = 1.0f / fmaxf(cnt, 1.0f);
        s.x *= inv; s.y *= inv; s.z *= inv; s.w *= inv;
        ((float4*)g_e_att)[idx] = s;
    }
}

// ---------------------------------------------------------------------------
// Kernel 3 (float4): one block (256 thr) per (i,r).
// ht[l] = (1/H) sum_h eA[h,l]*eB[h,l];  ht /= (sum_l ht + 1e-5)
// Writes SPLIT bf16 hi/lo A operand for the GEMM.
// ---------------------------------------------------------------------------
__global__ void k_ht_att(const int* __restrict__ hts, int n)
{
    int b = blockIdx.x;               // i*R + r
    int i = b / RR;
    int ha = hts[b * 2 + 0];
    int ta = hts[b * 2 + 1];

    const float4* A = (const float4*)(g_e_att + (size_t)(i * EE + ha) * HH * LN);
    const float4* B = (const float4*)(g_e_att + (size_t)(i * EE + ta) * HH * LN);
    int t = threadIdx.x;              // 256 threads, one float4 each

    float4 s = make_float4(0.f, 0.f, 0.f, 0.f);
#pragma unroll
    for (int hh = 0; hh < HH; hh++) {
        float4 a = A[hh * (LN / 4) + t];
        float4 c = B[hh * (LN / 4) + t];
        s.x += a.x * c.x; s.y += a.y * c.y; s.z += a.z * c.z; s.w += a.w * c.w;
    }
    const float invH = 1.0f / (float)HH;
    s.x *= invH; s.y *= invH; s.z *= invH; s.w *= invH;
    float local = s.x + s.y + s.z + s.w;

    __shared__ float red[8];
#pragma unroll
    for (int off = 16; off > 0; off >>= 1)
        local += __shfl_xor_sync(0xffffffffu, local, off);
    if ((t & 31) == 0) red[t >> 5] = local;
    __syncthreads();
    if (t < 32) {
        float x = (t < 8) ? red[t] : 0.0f;
#pragma unroll
        for (int off = 4; off > 0; off >>= 1)
            x += __shfl_xor_sync(0xffffffffu, x, off);
        if (t == 0) red[0] = x;
    }
    __syncthreads();
    float inv = 1.0f / (red[0] + 1e-5f);

    float4 o = make_float4(s.x * inv, s.y * inv, s.z * inv, s.w * inv);
    uint2 uh, ul;
    split4(o, uh, ul);
    ((uint2*)(g_A_hi + (size_t)b * LN))[t] = uh;
    ((uint2*)(g_A_lo + (size_t)b * LN))[t] = ul;
}

// ---------------------------------------------------------------------------
// Kernel 4: rs plane GEMM on tensor cores, split-bf16 3-term compensation:
//   C = Ahi*Bhi + Ahi*Blo + Alo*Bhi   (fp32 accum)
// Block tile 64(M) x 96(N), BK=32, 4 warps as 2(M) x 2(N) -> warp tile 32x48
// = acc[2][3] (6 independent accumulators). Per k-step: load ALL frags
// (2 A hi/lo, 3 B hi/lo), then mma TERM-OUTER so same-acc reuse distance = 6.
// grid = 8 x 4 x 4 = 128 blocks -> single wave. Fused hs/ts plane copy.
// ---------------------------------------------------------------------------
#define GBM 64
#define GBN 96
#define GBK 32
#define GT  128
#define LDA (GBK + 8)    // 40 bf16 row stride
#define LDB (GBN + 8)    // 104 bf16 row stride

__global__ __launch_bounds__(GT, 1) void k_gemm(const int* __restrict__ hts,
                                                float* __restrict__ out, int n)
{
    __shared__ __align__(16) __nv_bfloat16 Ah[2][GBM][LDA];
    __shared__ __align__(16) __nv_bfloat16 Al[2][GBM][LDA];
    __shared__ __align__(16) __nv_bfloat16 Bh[2][GBK][LDB];
    __shared__ __align__(16) __nv_bfloat16 Bl[2][GBK][LDB];

    int i = blockIdx.z;
    const __nv_bfloat16* Adh = g_A_hi + (size_t)i * RR * LN;
    const __nv_bfloat16* Adl = g_A_lo + (size_t)i * RR * LN;
    const __nv_bfloat16* Bdh = g_B_hi + (size_t)i * LN * DD;
    const __nv_bfloat16* Bdl = g_B_lo + (size_t)i * LN * DD;
    size_t P = (size_t)n * RR * DD;
    float* Cd = out + 2 * P + (size_t)i * RR * DD;      // R x D

    int rowBase = blockIdx.y * GBM;
    int colBase = blockIdx.x * GBN;
    int tid = threadIdx.x;
    int w   = tid >> 5;
    int wm  = w & 1;          // 0..1 : M slice (32 rows)
    int wn  = w >> 1;         // 0..1 : N slice (48 cols)

    // ---- loader slots (uint4 = 8 bf16) ----
    // A: 64 rows x 32 k / 8 = 256 slots per plane; 2 per thread
    int aR[2], aK[2];
#pragma unroll
    for (int s = 0; s < 2; s++) {
        int id = tid + s * GT;
        aR[s] = id >> 2; aK[s] = (id & 3) * 8;
    }
    // B: 32 k x 96 / 8 = 384 slots; 3 per thread
    int bR[3], bN[3];
#pragma unroll
    for (int s = 0; s < 3; s++) {
        int id = tid + s * GT;
        bR[s] = id / 12; bN[s] = (id % 12) * 8;
    }

    wmma::fragment<wmma::accumulator, 16, 16, 16, float> acc[2][3];
#pragma unroll
    for (int mi = 0; mi < 2; mi++)
#pragma unroll
        for (int j = 0; j < 3; j++) wmma::fill_fragment(acc[mi][j], 0.0f);

    // ---- initial global loads (k0 = 0) ----
    uint4 rah[2], ral[2], rbh[3], rbl[3];
#pragma unroll
    for (int s = 0; s < 2; s++) {
        rah[s] = *(const uint4*)&Adh[(size_t)(rowBase + aR[s]) * LN + aK[s]];
        ral[s] = *(const uint4*)&Adl[(size_t)(rowBase + aR[s]) * LN + aK[s]];
    }
#pragma unroll
    for (int s = 0; s < 3; s++) {
        rbh[s] = *(const uint4*)&Bdh[(size_t)bR[s] * DD + colBase + bN[s]];
        rbl[s] = *(const uint4*)&Bdl[(size_t)bR[s] * DD + colBase + bN[s]];
    }

    int buf = 0;
    for (int k0 = 0; k0 < LN; k0 += GBK) {
        // store prefetched regs into smem buffer `buf`
#pragma unroll
        for (int s = 0; s < 2; s++) {
            *(uint4*)&Ah[buf][aR[s]][aK[s]] = rah[s];
            *(uint4*)&Al[buf][aR[s]][aK[s]] = ral[s];
        }
#pragma unroll
        for (int s = 0; s < 3; s++) {
            *(uint4*)&Bh[buf][bR[s]][bN[s]] = rbh[s];
            *(uint4*)&Bl[buf][bR[s]][bN[s]] = rbl[s];
        }
        __syncthreads();

        // prefetch next K-slab
        int kn = k0 + GBK;
        if (kn < LN) {
#pragma unroll
            for (int s = 0; s < 2; s++) {
                rah[s] = *(const uint4*)&Adh[(size_t)(rowBase + aR[s]) * LN + kn + aK[s]];
                ral[s] = *(const uint4*)&Adl[(size_t)(rowBase + aR[s]) * LN + kn + aK[s]];
            }
#pragma unroll
            for (int s = 0; s < 3; s++) {
                rbh[s] = *(const uint4*)&Bdh[(size_t)(kn + bR[s]) * DD + colBase + bN[s]];
                rbl[s] = *(const uint4*)&Bdl[(size_t)(kn + bR[s]) * DD + colBase + bN[s]];
            }
        }

        // compute: 2 k-steps of 16; all frags loaded, then term-outer mma
#pragma unroll
        for (int kk = 0; kk < GBK / 16; kk++) {
            wmma::fragment<wmma::matrix_a, 16, 16, 16, __nv_bfloat16, wmma::row_major> fah[2], fal[2];
            wmma::fragment<wmma::matrix_b, 16, 16, 16, __nv_bfloat16, wmma::row_major> fbh[3], fbl[3];
#pragma unroll
            for (int mi = 0; mi < 2; mi++) {
                wmma::load_matrix_sync(fah[mi], &Ah[buf][wm * 32 + mi * 16][kk * 16], LDA);
                wmma::load_matrix_sync(fal[mi], &Al[buf][wm * 32 + mi * 16][kk * 16], LDA);
            }
#pragma unroll
            for (int j = 0; j < 3; j++) {
                wmma::load_matrix_sync(fbh[j], &Bh[buf][kk * 16][wn * 48 + j * 16], LDB);
                wmma::load_matrix_sync(fbl[j], &Bl[buf][kk * 16][wn * 48 + j * 16], LDB);
            }
            // term hh: 6 independent mmas
#pragma unroll
            for (int mi = 0; mi < 2; mi++)
#pragma unroll
                for (int j = 0; j < 3; j++)
                    wmma::mma_sync(acc[mi][j], fah[mi], fbh[j], acc[mi][j]);
            // term hl
#pragma unroll
            for (int mi = 0; mi < 2; mi++)
#pragma unroll
                for (int j = 0; j < 3; j++)
                    wmma::mma_sync(acc[mi][j], fah[mi], fbl[j], acc[mi][j]);
            // term lh
#pragma unroll
            for (int mi = 0; mi < 2; mi++)
#pragma unroll
                for (int j = 0; j < 3; j++)
                    wmma::mma_sync(acc[mi][j], fal[mi], fbh[j], acc[mi][j]);
        }
        buf ^= 1;
        __syncthreads();
    }

    // ---- epilogue: store accumulators ----
#pragma unroll
    for (int mi = 0; mi < 2; mi++)
#pragma unroll
        for (int j = 0; j < 3; j++) {
            float* c = &Cd[(size_t)(rowBase + wm * 32 + mi * 16) * DD
                           + colBase + wn * 48 + j * 16];
            wmma::store_matrix_sync(c, acc[mi][j], DD, wmma::mem_row_major);
        }

    // ---- fused hs/ts plane copy for this block's (row, col) tile ----
    {
        const float4* emb4 = (const float4*)g_e_emb;
        float4* out4 = (float4*)out;
        size_t P4 = (size_t)n * RR * (DD / 4);
        // tile = 64 rows x 24 float4 cols = 1536 float4 per plane; 12 per thread
#pragma unroll
        for (int s = 0; s < 12; s++) {
            int idx = tid + s * GT;        // 0..1535
            int row = idx / 24;            // 0..63
            int c4  = idx % 24;
            int b = i * RR + rowBase + row;
            int ha = hts[b * 2 + 0];
            int ta = hts[b * 2 + 1];
            int col4 = colBase / 4 + c4;
            float4 vh = emb4[(size_t)(i * EE + ha) * (DD / 4) + col4];
            float4 vt = emb4[(size_t)(i * EE + ta) * (DD / 4) + col4];
            out4[(size_t)b * (DD / 4) + col4]      = vh;
            out4[P4 + (size_t)b * (DD / 4) + col4] = vt;
        }
    }
}

// ---------------------------------------------------------------------------
extern "C" void kernel_launch(void* const* d_in, const int* in_sizes, int n_in,
                              void* d_out, int out_size)
{
    const float* seq  = (const float*)d_in[0];   // (n, L, d)
    const float* att  = (const float*)d_in[1];   // (n, h, L, L)
    const int*   pos  = (const int*)  d_in[2];   // (n, E, M)
    const float* mask = (const float*)d_in[3];   // (n, E, M)
    const int*   hts  = (const int*)  d_in[4];   // (n, R, 2)
    float* out = (float*)d_out;

    int n = in_sizes[0] / (LN * DD);
    if (n > NMAX) n = NMAX;

    {   // fused e_emb + split_seq + e_att
        k_pre<<<NB_EMB + NB_SPL + NB_EATT, 256>>>(seq, att, pos, mask, n);
    }
    {   // ht_att (writes split bf16 A)
        k_ht_att<<<n * RR, 256>>>(hts, n);
    }
    {   // rs plane GEMM (tensor cores, split-bf16, term-outer) + hs/ts copy
        dim3 grid(DD / GBN, RR / GBM, n);
        k_gemm<<<grid, GT>>>(hts, out, n);
    }
}

// round 8
// speedup vs baseline: 1.4085x; 1.0006x over previous
#include <cuda_runtime.h>
#include <cuda_bf16.h>
#include <mma.h>
#include <float.h>

using namespace nvcuda;

// Problem constants (fixed by reference setup_inputs)
#define LN   1024      // sequence length L
#define DD   768       // hidden d
#define HH   12        // heads
#define EE   32        // entities
#define MM   4         // mentions
#define RR   256       // relations per doc
#define NMAX 4         // batch

// Scratch (device globals -- no allocation allowed)
__device__ float g_e_emb[NMAX * EE * DD];            // (n,E,d)
__device__ float g_e_att[NMAX * EE * HH * LN];       // (n,E,h,L)

// split-bf16 operands for the rs GEMM
__device__ __align__(16) __nv_bfloat16 g_A_hi[NMAX * RR * LN];   // ht_att hi
__device__ __align__(16) __nv_bfloat16 g_A_lo[NMAX * RR * LN];   // ht_att lo
__device__ __align__(16) __nv_bfloat16 g_B_hi[NMAX * LN * DD];   // seq hi
__device__ __align__(16) __nv_bfloat16 g_B_lo[NMAX * LN * DD];   // seq lo

// ---------------------------------------------------------------------------
// split helper: float4 -> 4 hi bf16 (uint2) + 4 lo bf16 (uint2)
// ---------------------------------------------------------------------------
__device__ __forceinline__ void split4(float4 v, uint2& uh, uint2& ul)
{
    __nv_bfloat162 h01 = __float22bfloat162_rn(make_float2(v.x, v.y));
    __nv_bfloat162 h23 = __float22bfloat162_rn(make_float2(v.z, v.w));
    float2 f01 = __bfloat1622float2(h01);
    float2 f23 = __bfloat1622float2(h23);
    __nv_bfloat162 l01 = __float22bfloat162_rn(make_float2(v.x - f01.x, v.y - f01.y));
    __nv_bfloat162 l23 = __float22bfloat162_rn(make_float2(v.z - f23.x, v.w - f23.y));
    uh.x = *(unsigned*)&h01; uh.y = *(unsigned*)&h23;
    ul.x = *(unsigned*)&l01; ul.y = *(unsigned*)&l23;
}

// ---------------------------------------------------------------------------
// Fused pre-kernel: e_emb | split_seq | e_att, dispatched by blockIdx range.
// split & e_att sections process TWO elements per thread (idx, idx+half)
// to double memory-level parallelism (they are DRAM-latency bound).
// ---------------------------------------------------------------------------
#define NB_EMB   ((NMAX * EE * DD) / 256)                   // 384
#define NB_SPL   ((NMAX * LN * DD / 4) / 2 / 256)           // 1536
#define NB_EATT  ((NMAX * EE * HH * (LN / 4)) / 2 / 256)    // 768

__global__ void k_pre(const float* __restrict__ seq,
                      const float* __restrict__ att,
                      const int*   __restrict__ pos,
                      const float* __restrict__ mask,
                      int n)
{
    int blk = blockIdx.x;
    if (blk < NB_EMB) {
        // ---- e_emb ----
        int idx = blk * 256 + threadIdx.x;
        int total = n * EE * DD;
        if (idx >= total) return;
        int k = idx % DD;
        int e = (idx / DD) % EE;
        int i = idx / (DD * EE);
        const int*   p  = pos  + (i * EE + e) * MM;
        const float* mk = mask + (i * EE + e) * MM;
        float v[MM];
        float mx = -FLT_MAX;
#pragma unroll
        for (int m = 0; m < MM; m++) {
            int pp = p[m] + 1;                       // OFFSET
            float x = seq[(i * LN + pp) * DD + k];
            if (mk[m] <= 0.0f) x = -FLT_MAX;
            v[m] = x;
            mx = fmaxf(mx, x);
        }
        float s = 0.0f;
#pragma unroll
        for (int m = 0; m < MM; m++) s += expf(v[m] - mx);
        g_e_emb[idx] = mx + logf(s);
    } else if (blk < NB_EMB + NB_SPL) {
        // ---- split seq into bf16 hi/lo (2 float4 per thread) ----
        int half = n * LN * DD / 4 / 2;
        int idx = (blk - NB_EMB) * 256 + threadIdx.x;
        if (idx >= half) return;
        float4 v0 = ((const float4*)seq)[idx];
        float4 v1 = ((const float4*)seq)[idx + half];
        uint2 uh, ul;
        split4(v0, uh, ul);
        ((uint2*)g_B_hi)[idx] = uh;
        ((uint2*)g_B_lo)[idx] = ul;
        split4(v1, uh, ul);
        ((uint2*)g_B_hi)[idx + half] = uh;
        ((uint2*)g_B_lo)[idx + half] = ul;
    } else {
        // ---- e_att (2 float4 per thread) ----
        int half = n * EE * HH * (LN / 4) / 2;
        int base = (blk - NB_EMB - NB_SPL) * 256 + threadIdx.x;
        if (base >= half) return;
#pragma unroll
        for (int u = 0; u < 2; u++) {
            int idx = base + u * half;
            int l4 = idx % (LN / 4);
            int hh = (idx / (LN / 4)) % HH;
            int e  = (idx / ((LN / 4) * HH)) % EE;
            int i  = idx / ((LN / 4) * HH * EE);
            const int*   p  = pos  + (i * EE + e) * MM;
            const float* mk = mask + (i * EE + e) * MM;
            const float4* att4 = (const float4*)att;
            float cnt = 0.0f;
            float4 s = make_float4(0.f, 0.f, 0.f, 0.f);
#pragma unroll
            for (int m = 0; m < MM; m++) {
                float mm = mk[m];
                cnt += mm;
                int pp = p[m] + 1;
                float4 a = att4[((size_t)(i * HH + hh) * LN + pp) * (LN / 4) + l4];
                s.x += mm * a.x; s.y += mm * a.y; s.z += mm * a.z; s.w += mm * a.w;
            }
            float inv = 1.0f / fmaxf(cnt, 1.0f);
            s.x *= inv; s.y *= inv; s.z *= inv; s.w *= inv;
            ((float4*)g_e_att)[idx] = s;
        }
    }
}

// ---------------------------------------------------------------------------
// Kernel 3 (float4): one block (256 thr) per (i,r).
// ht[l] = (1/H) sum_h eA[h,l]*eB[h,l];  ht /= (sum_l ht + 1e-5)
// Writes SPLIT bf16 hi/lo A operand for the GEMM.
// ---------------------------------------------------------------------------
__global__ void k_ht_att(const int* __restrict__ hts, int n)
{
    int b = blockIdx.x;               // i*R + r
    int i = b / RR;
    int ha = hts[b * 2 + 0];
    int ta = hts[b * 2 + 1];

    const float4* A = (const float4*)(g_e_att + (size_t)(i * EE + ha) * HH * LN);
    const float4* B = (const float4*)(g_e_att + (size_t)(i * EE + ta) * HH * LN);
    int t = threadIdx.x;              // 256 threads, one float4 each

    float4 s = make_float4(0.f, 0.f, 0.f, 0.f);
#pragma unroll
    for (int hh = 0; hh < HH; hh++) {
        float4 a = A[hh * (LN / 4) + t];
        float4 c = B[hh * (LN / 4) + t];
        s.x += a.x * c.x; s.y += a.y * c.y; s.z += a.z * c.z; s.w += a.w * c.w;
    }
    const float invH = 1.0f / (float)HH;
    s.x *= invH; s.y *= invH; s.z *= invH; s.w *= invH;
    float local = s.x + s.y + s.z + s.w;

    __shared__ float red[8];
#pragma unroll
    for (int off = 16; off > 0; off >>= 1)
        local += __shfl_xor_sync(0xffffffffu, local, off);
    if ((t & 31) == 0) red[t >> 5] = local;
    __syncthreads();
    if (t < 32) {
        float x = (t < 8) ? red[t] : 0.0f;
#pragma unroll
        for (int off = 4; off > 0; off >>= 1)
            x += __shfl_xor_sync(0xffffffffu, x, off);
        if (t == 0) red[0] = x;
    }
    __syncthreads();
    float inv = 1.0f / (red[0] + 1e-5f);

    float4 o = make_float4(s.x * inv, s.y * inv, s.z * inv, s.w * inv);
    uint2 uh, ul;
    split4(o, uh, ul);
    ((uint2*)(g_A_hi + (size_t)b * LN))[t] = uh;
    ((uint2*)(g_A_lo + (size_t)b * LN))[t] = ul;
}

// ---------------------------------------------------------------------------
// Kernel 4: rs plane GEMM on tensor cores, split-bf16 3-term compensation:
//   C = Ahi*Bhi + Ahi*Blo + Alo*Bhi   (fp32 accum)
// Block 64(M) x 96(N), BK=32, 8 warps as 4(M) x 2(N) -> warp tile 16x48
// (3 independent accs / warp). TERM-OUTER mma order (reuse distance 3) AND
// 2 warps per SMSP for latency overlap (R6 had 8 warps + distance-1; R7 had
// distance-6 + only 1 warp/SMSP; this takes both).
// grid = 8 x 4 x 4 = 128 blocks -> single wave. Fused hs/ts plane copy.
// ---------------------------------------------------------------------------
#define GBM 64
#define GBN 96
#define GBK 32
#define GT  256
#define LDA (GBK + 8)    // 40 bf16 row stride
#define LDB (GBN + 8)    // 104 bf16 row stride

__global__ __launch_bounds__(GT, 1) void k_gemm(const int* __restrict__ hts,
                                                float* __restrict__ out, int n)
{
    __shared__ __align__(16) __nv_bfloat16 Ah[2][GBM][LDA];
    __shared__ __align__(16) __nv_bfloat16 Al[2][GBM][LDA];
    __shared__ __align__(16) __nv_bfloat16 Bh[2][GBK][LDB];
    __shared__ __align__(16) __nv_bfloat16 Bl[2][GBK][LDB];

    int i = blockIdx.z;
    const __nv_bfloat16* Adh = g_A_hi + (size_t)i * RR * LN;
    const __nv_bfloat16* Adl = g_A_lo + (size_t)i * RR * LN;
    const __nv_bfloat16* Bdh = g_B_hi + (size_t)i * LN * DD;
    const __nv_bfloat16* Bdl = g_B_lo + (size_t)i * LN * DD;
    size_t P = (size_t)n * RR * DD;
    float* Cd = out + 2 * P + (size_t)i * RR * DD;      // R x D

    int rowBase = blockIdx.y * GBM;
    int colBase = blockIdx.x * GBN;
    int tid = threadIdx.x;
    int w   = tid >> 5;
    int wm  = w & 3;          // 0..3 : M slice (16 rows)
    int wn  = w >> 2;         // 0..1 : N slice (48 cols)

    // ---- loader slots (uint4 = 8 bf16) ----
    // A: 64 rows x 32 k / 8 = 256 slots per plane; 1 per thread
    int aRow = tid >> 2, aK8 = (tid & 3) * 8;
    // B: 32 k x 96 / 8 = 384 slots; slot tid, plus tid+256 for tid<128
    int b0Row = tid / 12,         b0N = (tid % 12) * 8;
    int b1Row = (tid + 256) / 12, b1N = ((tid + 256) % 12) * 8;
    bool hasB1 = tid < 128;

    wmma::fragment<wmma::accumulator, 16, 16, 16, float> acc[3];
#pragma unroll
    for (int j = 0; j < 3; j++) wmma::fill_fragment(acc[j], 0.0f);

    // ---- initial global loads (k0 = 0) ----
    uint4 rah, ral, rbh0, rbl0, rbh1, rbl1;
    rah = *(const uint4*)&Adh[(size_t)(rowBase + aRow) * LN + aK8];
    ral = *(const uint4*)&Adl[(size_t)(rowBase + aRow) * LN + aK8];
    rbh0 = *(const uint4*)&Bdh[(size_t)b0Row * DD + colBase + b0N];
    rbl0 = *(const uint4*)&Bdl[(size_t)b0Row * DD + colBase + b0N];
    if (hasB1) {
        rbh1 = *(const uint4*)&Bdh[(size_t)b1Row * DD + colBase + b1N];
        rbl1 = *(const uint4*)&Bdl[(size_t)b1Row * DD + colBase + b1N];
    }

    int buf = 0;
    for (int k0 = 0; k0 < LN; k0 += GBK) {
        // store prefetched regs into smem buffer `buf`
        *(uint4*)&Ah[buf][aRow][aK8] = rah;
        *(uint4*)&Al[buf][aRow][aK8] = ral;
        *(uint4*)&Bh[buf][b0Row][b0N] = rbh0;
        *(uint4*)&Bl[buf][b0Row][b0N] = rbl0;
        if (hasB1) {
            *(uint4*)&Bh[buf][b1Row][b1N] = rbh1;
            *(uint4*)&Bl[buf][b1Row][b1N] = rbl1;
        }
        __syncthreads();

        // prefetch next K-slab
        int kn = k0 + GBK;
        if (kn < LN) {
            rah = *(const uint4*)&Adh[(size_t)(rowBase + aRow) * LN + kn + aK8];
            ral = *(const uint4*)&Adl[(size_t)(rowBase + aRow) * LN + kn + aK8];
            rbh0 = *(const uint4*)&Bdh[(size_t)(kn + b0Row) * DD + colBase + b0N];
            rbl0 = *(const uint4*)&Bdl[(size_t)(kn + b0Row) * DD + colBase + b0N];
            if (hasB1) {
                rbh1 = *(const uint4*)&Bdh[(size_t)(kn + b1Row) * DD + colBase + b1N];
                rbl1 = *(const uint4*)&Bdl[(size_t)(kn + b1Row) * DD + colBase + b1N];
            }
        }

        // compute: 2 k-steps of 16; load all frags, then TERM-OUTER mma
#pragma unroll
        for (int kk = 0; kk < GBK / 16; kk++) {
            wmma::fragment<wmma::matrix_a, 16, 16, 16, __nv_bfloat16, wmma::row_major> fah, fal;
            wmma::fragment<wmma::matrix_b, 16, 16, 16, __nv_bfloat16, wmma::row_major> fbh[3], fbl[3];
            wmma::load_matrix_sync(fah, &Ah[buf][wm * 16][kk * 16], LDA);
            wmma::load_matrix_sync(fal, &Al[buf][wm * 16][kk * 16], LDA);
#pragma unroll
            for (int j = 0; j < 3; j++) {
                wmma::load_matrix_sync(fbh[j], &Bh[buf][kk * 16][wn * 48 + j * 16], LDB);
                wmma::load_matrix_sync(fbl[j], &Bl[buf][kk * 16][wn * 48 + j * 16], LDB);
            }
            // term hh (3 independent), then hl, then lh: reuse distance 3
#pragma unroll
            for (int j = 0; j < 3; j++)
                wmma::mma_sync(acc[j], fah, fbh[j], acc[j]);
#pragma unroll
            for (int j = 0; j < 3; j++)
                wmma::mma_sync(acc[j], fah, fbl[j], acc[j]);
#pragma unroll
            for (int j = 0; j < 3; j++)
                wmma::mma_sync(acc[j], fal, fbh[j], acc[j]);
        }
        buf ^= 1;
        __syncthreads();
    }

    // ---- epilogue: store accumulators ----
#pragma unroll
    for (int j = 0; j < 3; j++) {
        float* c = &Cd[(size_t)(rowBase + wm * 16) * DD + colBase + wn * 48 + j * 16];
        wmma::store_matrix_sync(c, acc[j], DD, wmma::mem_row_major);
    }

    // ---- fused hs/ts plane copy for this block's (row, col) tile ----
    {
        const float4* emb4 = (const float4*)g_e_emb;
        float4* out4 = (float4*)out;
        size_t P4 = (size_t)n * RR * (DD / 4);
        // tile = 64 rows x 24 float4 cols = 1536 float4 per plane; 6 per thread
#pragma unroll
        for (int s = 0; s < 6; s++) {
            int idx = tid + s * GT;        // 0..1535
            int row = idx / 24;            // 0..63
            int c4  = idx % 24;
            int b = i * RR + rowBase + row;
            int ha = hts[b * 2 + 0];
            int ta = hts[b * 2 + 1];
            int col4 = colBase / 4 + c4;
            float4 vh = emb4[(size_t)(i * EE + ha) * (DD / 4) + col4];
            float4 vt = emb4[(size_t)(i * EE + ta) * (DD / 4) + col4];
            out4[(size_t)b * (DD / 4) + col4]      = vh;
            out4[P4 + (size_t)b * (DD / 4) + col4] = vt;
        }
    }
}

// ---------------------------------------------------------------------------
extern "C" void kernel_launch(void* const* d_in, const int* in_sizes, int n_in,
                              void* d_out, int out_size)
{
    const float* seq  = (const float*)d_in[0];   // (n, L, d)
    const float* att  = (const float*)d_in[1];   // (n, h, L, L)
    const int*   pos  = (const int*)  d_in[2];   // (n, E, M)
    const float* mask = (const float*)d_in[3];   // (n, E, M)
    const int*   hts  = (const int*)  d_in[4];   // (n, R, 2)
    float* out = (float*)d_out;

    int n = in_sizes[0] / (LN * DD);
    if (n > NMAX) n = NMAX;

    {   // fused e_emb + split_seq + e_att
        k_pre<<<NB_EMB + NB_SPL + NB_EATT, 256>>>(seq, att, pos, mask, n);
    }
    {   // ht_att (writes split bf16 A)
        k_ht_att<<<n * RR, 256>>>(hts, n);
    }
    {   // rs plane GEMM (tensor cores, 8 warps, term-outer) + hs/ts copy
        dim3 grid(DD / GBN, RR / GBM, n);
        k_gemm<<<grid, GT>>>(hts, out, n);
    }
}